// round 1
// baseline (speedup 1.0000x reference)
#include <cuda_runtime.h>
#include <math.h>

// Problem constants (fixed by the dataset)
#define C_DIM   16
#define DK_DIM  8
#define NB_DIM  10
#define JDIM    16          // DIM_SH
#define NMAX    20000
#define EMAX    50000
#define AFEAT   4096        // 2 nets * 128 (jo) * 16 (t)

// Scratch (device globals — allocation-free)
__device__ float g_A[(size_t)NMAX * AFEAT];   // [n][net][jo][t], t fastest
__device__ float g_Wp[2 * 2048 * 16];         // [f = net*2048 + jo*16 + t][c]
__device__ float g_q[NMAX * DK_DIM];
__device__ float g_expv[EMAX];
__device__ float g_v[EMAX * DK_DIM];
__device__ float g_z[NMAX];

// ---------------------------------------------------------------------------
// k0: permute Wk2/Wv2 ([16, 2048] with col index (c*128 + j*8 + o)) into
//     Wp[f][c] where f = net*2048 + jo*16 + t (matches A layout, coalesced).
__global__ void permute_w_kernel(const float* __restrict__ Wk2,
                                 const float* __restrict__ Wv2) {
    int idx = blockIdx.x * blockDim.x + threadIdx.x;   // 65536 threads
    if (idx >= 65536) return;
    int c   = idx & 15;
    int f   = idx >> 4;
    int t   = f & 15;
    int jo  = (f >> 4) & 127;
    int net = f >> 11;
    const float* W = net ? Wv2 : Wk2;
    g_Wp[f * 16 + c] = W[t * 2048 + c * 128 + jo];
}

// ---------------------------------------------------------------------------
// k1: q = x @ Wq   [N,16]@[16,8]
__global__ void q_kernel(const float* __restrict__ x,
                         const float* __restrict__ Wq, int N) {
    int i = blockIdx.x * blockDim.x + threadIdx.x;
    if (i >= N * DK_DIM) return;
    int n = i >> 3, o = i & 7;
    float s = 0.f;
#pragma unroll
    for (int c = 0; c < C_DIM; c++) s += x[n * C_DIM + c] * Wq[c * DK_DIM + o];
    g_q[i] = s;
}

// ---------------------------------------------------------------------------
// k2: A[n][f] = sum_c x[n,c] * Wp[f][c]   (node tile 32, output tile 256)
__global__ void __launch_bounds__(256) a_gemm_kernel(const float* __restrict__ x, int N) {
    __shared__ float xs[32][16];
    int tid = threadIdx.x;
    int n0  = blockIdx.x * 32;
    for (int i = tid; i < 512; i += 256) {
        int n = i >> 4, c = i & 15;
        int g = n0 + n;
        xs[n][c] = (g < N) ? x[g * C_DIM + c] : 0.f;
    }
    __syncthreads();

    int f = blockIdx.y * 256 + tid;                     // 0..4095
    const float4* wr = (const float4*)&g_Wp[f * 16];
    float4 w0 = wr[0], w1 = wr[1], w2 = wr[2], w3 = wr[3];

    int nmax = N - n0; if (nmax > 32) nmax = 32;
    for (int n = 0; n < nmax; n++) {
        const float* xr = xs[n];
        float s = w0.x * xr[0]  + w0.y * xr[1]  + w0.z * xr[2]  + w0.w * xr[3]
                + w1.x * xr[4]  + w1.y * xr[5]  + w1.z * xr[6]  + w1.w * xr[7]
                + w2.x * xr[8]  + w2.y * xr[9]  + w2.z * xr[10] + w2.w * xr[11]
                + w3.x * xr[12] + w3.y * xr[13] + w3.z * xr[14] + w3.w * xr[15];
        g_A[(size_t)(n0 + n) * AFEAT + f] = s;
    }
}

// ---------------------------------------------------------------------------
// k3: edge pass 1 — one warp per edge.
//  emb/cutoff/sh/h, gather A[src], contract, logits, atomicAdd z, store expv/v.
__global__ void __launch_bounds__(256) edge_pass1_kernel(
    const float* __restrict__ pos,
    const float* __restrict__ Wk1, const float* __restrict__ Wv1,
    const int* __restrict__ esrc, const int* __restrict__ edst, int E) {

    __shared__ float hsm[8][32];   // [warp][net*16 + t]
    __shared__ float shsm[8][16];  // [warp][j]

    int warp = threadIdx.x >> 5;
    int lane = threadIdx.x & 31;
    int e = blockIdx.x * 8 + warp;
    if (e >= E) return;            // warp-uniform

    int src = esrc[e], dst = edst[e];

    float vx = pos[src * 3 + 0] - pos[dst * 3 + 0];
    float vy = pos[src * 3 + 1] - pos[dst * 3 + 1];
    float vz = pos[src * 3 + 2] - pos[dst * 3 + 2];
    float r2  = vx * vx + vy * vy + vz * vz;
    float rsh = sqrtf(r2);
    float inv = 1.f / fmaxf(rsh, 1e-9f);
    float ux = vx * inv, uy = vy * inv, uz = vz * inv;
    float r = sqrtf(r2 + 1e-18f);

    // spherical harmonics l=0..3 (component normalization)
    float xx = ux * ux, yy = uy * uy, zz = uz * uz;
    if (lane == 0) {
        float* S = shsm[warp];
        S[0]  = 1.f;
        S[1]  = 1.7320508f * ux;
        S[2]  = 1.7320508f * uy;
        S[3]  = 1.7320508f * uz;
        S[4]  = 3.8729833f * ux * uy;
        S[5]  = 3.8729833f * uy * uz;
        S[6]  = 1.1180340f * (3.f * zz - 1.f);
        S[7]  = 3.8729833f * ux * uz;
        S[8]  = 1.9364917f * (xx - yy);
        S[9]  = 2.0916501f * uy * (3.f * xx - yy);
        S[10] = 10.2469508f * ux * uy * uz;
        S[11] = 1.6201852f * uy * (5.f * zz - 1.f);
        S[12] = 1.3228757f * uz * (5.f * zz - 3.f);
        S[13] = 1.6201852f * ux * (5.f * zz - 1.f);
        S[14] = 5.1234754f * uz * (xx - yy);
        S[15] = 2.0916501f * ux * (xx - 3.f * yy);
    }

    // radial embedding + fcnet hidden: lanes 0..15 -> h_k[t], 16..31 -> h_v[t]
    {
        const float step = 3.5f / 11.f;
        const float EMB_K = 1.14136f * 7.3890561f * 3.16227766f; // 1.14136*e^2*sqrt(10)
        float rs = r / step;
        float emb[NB_DIM];
#pragma unroll
        for (int b = 0; b < NB_DIM; b++) {
            float u = rs - (float)(b + 1);
            float y = 0.f;
            if (fabsf(u) < 1.f) y = expf(-1.f / (1.f - u * u));
            emb[b] = EMB_K * y;
        }
        int net = lane >> 4, t = lane & 15;
        const float* W1 = net ? Wv1 : Wk1;
        float d = 0.f;
#pragma unroll
        for (int b = 0; b < NB_DIM; b++) d += emb[b] * W1[b * 16 + t];
        d *= 0.316227766f;                 // / sqrt(10)
        hsm[warp][lane] = d / (1.f + expf(-d));   // silu
    }
    __syncwarp();

    const float* Abase = g_A + (size_t)src * AFEAT;
    float q_o = g_q[dst * DK_DIM + (lane & 7)];
    int Lj = lane >> 3;                     // j base for this lane
    float results[2];

#pragma unroll
    for (int net = 0; net < 2; net++) {
        const float* Ab = Abase + net * 2048;
        const float* hh = hsm[warp] + net * 16;
        float kp = 0.f;
#pragma unroll
        for (int jj = 0; jj < 4; jj++) {
            int jo = lane + 32 * jj;        // j = Lj + 4*jj, o = lane&7
            const float4* ap = (const float4*)(Ab + jo * 16);
            float p = 0.f;
#pragma unroll
            for (int tt = 0; tt < 4; tt++) {
                float4 a = ap[tt];
                p += a.x * hh[4 * tt + 0] + a.y * hh[4 * tt + 1]
                   + a.z * hh[4 * tt + 2] + a.w * hh[4 * tt + 3];
            }
            kp += p * shsm[warp][Lj + 4 * jj];
        }
        kp += __shfl_xor_sync(0xffffffffu, kp, 8);
        kp += __shfl_xor_sync(0xffffffffu, kp, 16);
        results[net] = kp * (1.f / 64.f);   // /sqrt(16) from fcnet, /sqrt(256) norm
    }

    if (lane < 8) g_v[e * DK_DIM + lane] = results[1];

    float prod = results[0] * q_o;
    prod += __shfl_xor_sync(0xffffffffu, prod, 1);
    prod += __shfl_xor_sync(0xffffffffu, prod, 2);
    prod += __shfl_xor_sync(0xffffffffu, prod, 4);

    if (lane == 0) {
        float logit = prod * 0.35355339f;   // / sqrt(8)
        float tcut = 10.f * (1.f - r * (1.f / 3.5f));
        float cut = (tcut > 0.f) ? expf(-1.f / tcut) : 0.f;
        float ev = cut * expf(logit);
        g_expv[e] = ev;
        atomicAdd(&g_z[dst], ev);
    }
}

// ---------------------------------------------------------------------------
// k4: scatter out[dst] += sqrt(relu(alpha)) * v
__global__ void scatter_kernel(const int* __restrict__ edst,
                               float* __restrict__ out, int E) {
    int i = blockIdx.x * blockDim.x + threadIdx.x;
    if (i >= E * DK_DIM) return;
    int e = i >> 3;
    int dst = edst[e];
    float z = g_z[dst];
    if (z == 0.f) z = 1.f;
    float a = g_expv[e] / z;
    float w = sqrtf(a);                    // alpha >= 0 always
    atomicAdd(&out[dst * DK_DIM + (i & 7)], w * g_v[i]);
}

// ---------------------------------------------------------------------------
extern "C" void kernel_launch(void* const* d_in, const int* in_sizes, int n_in,
                              void* d_out, int out_size) {
    const float* pos = (const float*)d_in[0];
    const float* x   = (const float*)d_in[1];
    const float* Wq  = (const float*)d_in[2];
    const float* Wk1 = (const float*)d_in[3];
    const float* Wk2 = (const float*)d_in[4];
    const float* Wv1 = (const float*)d_in[5];
    const float* Wv2 = (const float*)d_in[6];
    const int* esrc  = (const int*)d_in[7];
    const int* edst  = (const int*)d_in[8];

    int N = in_sizes[1] / C_DIM;
    int E = in_sizes[7];
    float* out = (float*)d_out;

    void* zptr = nullptr;
    cudaGetSymbolAddress(&zptr, g_z);
    cudaMemsetAsync(zptr, 0, (size_t)N * sizeof(float));
    cudaMemsetAsync(out, 0, (size_t)out_size * sizeof(float));

    permute_w_kernel<<<256, 256>>>(Wk2, Wv2);
    q_kernel<<<(N * DK_DIM + 255) / 256, 256>>>(x, Wq, N);

    dim3 ga((N + 31) / 32, AFEAT / 256);
    a_gemm_kernel<<<ga, 256>>>(x, N);

    edge_pass1_kernel<<<(E + 7) / 8, 256>>>(pos, Wk1, Wv1, esrc, edst, E);
    scatter_kernel<<<(E * DK_DIM + 255) / 256, 256>>>(edst, out, E);
}